// round 4
// baseline (speedup 1.0000x reference)
#include <cuda_runtime.h>
#include <math.h>

#define NPB   120000                 // points per batch
#define NB    8                      // batches
#define NPTS  (NPB*NB)               // 960000
#define GX    704
#define GY    800
#define GZ    20
#define BIGC  (GX*GY*GZ)             // 11,264,000 cells per batch
#define MAXV  40000
#define MAXP  10
#define SENT  0x7FFFFFFF

// Output layout (float32), concatenated in reference return order:
#define OFF_VOX 0                          // 8*40000*10*4 = 12,800,000
#define OFF_NP  12800000                   // 8*40000      =    320,000
#define OFF_CO  13120000                   // 8*40000*4    =  1,280,000
#define OFF_GS  14400000                   // 3

// Scratch (device globals: allocation-free per harness rules)
__device__ int           g_cell[NB * BIGC];          // ~360 MB: leader idx -> slot/sentinel
__device__ int           g_vox [NB * MAXV * MAXP];   // 12.8 MB: sorted point-idx lists
__device__ int           g_key [NPTS];               // global cell key per point (SENT if invalid)
__device__ unsigned char g_flag[NPTS];               // leader flag per point

// K1: compute keys, clear touched cells, clear voxel lists
__global__ void k_prep(const float* __restrict__ pts, int n) {
    int i = blockIdx.x * blockDim.x + threadIdx.x;
    if (i < NB * MAXV * MAXP) g_vox[i] = SENT;
    if (i >= n) return;
    float x = pts[i*5 + 1];
    float y = pts[i*5 + 2];
    float z = pts[i*5 + 3];
    // match XLA: floor((p - pc_min) / vsize), IEEE division regardless of fast-math
    int cx = (int)floorf(__fdiv_rn(__fadd_rn(x,  0.0f), 0.1f));
    int cy = (int)floorf(__fdiv_rn(__fadd_rn(y, 40.0f), 0.1f));
    int cz = (int)floorf(__fdiv_rn(__fadd_rn(z,  3.0f), 0.2f));
    int key = SENT;
    if (cx >= 0 && cx < GX && cy >= 0 && cy < GY && cz >= 0 && cz < GZ) {
        int b = i / NPB;
        key = b * BIGC + (cz * GY + cy) * GX + cx;
        g_cell[key] = SENT;           // clear only touched cells
    }
    g_key[i] = key;
}

// K2: per-cell leader = min original (local) index
__global__ void k_min(int n) {
    int i = blockIdx.x * blockDim.x + threadIdx.x;
    if (i >= n) return;
    int key = g_key[i];
    if (key == SENT) return;
    atomicMin(&g_cell[key], i % NPB);
}

// K3: one block per batch. Flag leaders, exclusive-scan leader flags to assign
// first-come slots, write slot (or SENT if >= MAXV) back into the cell.
__global__ void k_scan() {
    const int b    = blockIdx.x;
    const int t    = threadIdx.x;
    const int C    = (NPB + 1023) / 1024;   // 118 points per thread
    const int base = b * NPB;
    const int lo   = t * C;
    const int hi   = (lo + C < NPB) ? (lo + C) : NPB;

    int cnt = 0;
    for (int p = lo; p < hi; p++) {
        int key = g_key[base + p];
        unsigned char f = 0;
        if (key != SENT && g_cell[key] == p) f = 1;
        g_flag[base + p] = f;
        cnt += f;
    }

    // block-wide exclusive scan of per-thread leader counts (1024 = 32 warps)
    __shared__ int wsum[32];
    int lane = t & 31, wid = t >> 5;
    int v = cnt;
    #pragma unroll
    for (int o = 1; o < 32; o <<= 1) {
        int nv = __shfl_up_sync(0xFFFFFFFFu, v, o);
        if (lane >= o) v += nv;
    }
    if (lane == 31) wsum[wid] = v;
    __syncthreads();                         // also orders phase-1 reads before phase-3 writes
    if (wid == 0) {
        int w = wsum[lane];
        #pragma unroll
        for (int o = 1; o < 32; o <<= 1) {
            int nw = __shfl_up_sync(0xFFFFFFFFu, w, o);
            if (lane >= o) w += nw;
        }
        wsum[lane] = w;
    }
    __syncthreads();
    int run = v - cnt + ((wid > 0) ? wsum[wid - 1] : 0);

    for (int p = lo; p < hi; p++) {
        if (g_flag[base + p]) {
            int key = g_key[base + p];
            g_cell[key] = (run < MAXV) ? run : SENT;
            run++;
        }
    }
}

// K4: lock-free sorted insertion of point index into its voxel's 10-entry list.
// Final state = 10 smallest original indices in ascending order (deterministic).
__global__ void k_insert(int n) {
    int i = blockIdx.x * blockDim.x + threadIdx.x;
    if (i >= n) return;
    int key = g_key[i];
    if (key == SENT) return;
    int s = g_cell[key];
    if (s == SENT) return;
    int b = i / NPB;
    int* list = &g_vox[(b * MAXV + s) * MAXP];
    int carry = i % NPB;
    #pragma unroll
    for (int j = 0; j < MAXP; j++) {
        int old = atomicMin(&list[j], carry);
        if (old == SENT) break;              // took an empty tail slot
        carry = (old > carry) ? old : carry; // displaced value moves right
    }
}

// K5: write all outputs (covers every element; d_out is poisoned)
__global__ void k_fill(const float* __restrict__ pts, float* __restrict__ out) {
    int v = blockIdx.x * blockDim.x + threadIdx.x;
    if (v == 0) {
        out[OFF_GS + 0] = 704.0f;
        out[OFF_GS + 1] = 800.0f;
        out[OFF_GS + 2] = 20.0f;
    }
    if (v >= NB * MAXV) return;
    int b = v / MAXV;
    const int* list = &g_vox[v * MAXP];
    float* vox = out + OFF_VOX + (size_t)v * MAXP * 4;
    int cnt = 0;
    int idx0 = list[0];
    #pragma unroll
    for (int j = 0; j < MAXP; j++) {
        int idx = list[j];
        float4 r = make_float4(0.f, 0.f, 0.f, 0.f);
        if (idx != SENT) {
            const float* p = pts + (size_t)(b * NPB + idx) * 5 + 1;
            r = make_float4(p[0], p[1], p[2], p[3]);
            cnt++;
        }
        ((float4*)vox)[j] = r;   // 160B-aligned base per voxel
    }
    out[OFF_NP + v] = (float)cnt;

    float cb = (float)b, cz = -1.f, cy = -1.f, cx = -1.f;
    if (cnt > 0) {
        int lid = g_key[b * NPB + idx0] - b * BIGC;
        int x = lid % GX;
        int t2 = lid / GX;
        int y = t2 % GY;
        int z = t2 / GY;
        cz = (float)z; cy = (float)y; cx = (float)x;
    }
    float4* cr = (float4*)(out + OFF_CO + (size_t)v * 4);
    *cr = make_float4(cb, cz, cy, cx);
}

extern "C" void kernel_launch(void* const* d_in, const int* in_sizes, int n_in,
                              void* d_out, int out_size) {
    const float* pts = (const float*)d_in[0];
    int n = in_sizes[0] / 5;                 // 960000
    float* out = (float*)d_out;

    const int T = 256;
    int prep_work = NB * MAXV * MAXP;        // 3.2M (covers both clears + points)
    if (prep_work < n) prep_work = n;

    k_prep  <<<(prep_work + T - 1) / T, T>>>(pts, n);
    k_min   <<<(n + T - 1) / T, T>>>(n);
    k_scan  <<<NB, 1024>>>();
    k_insert<<<(n + T - 1) / T, T>>>(n);
    k_fill  <<<(NB * MAXV + T - 1) / T, T>>>(pts, out);
}

// round 5
// speedup vs baseline: 4.1070x; 4.1070x over previous
#include <cuda_runtime.h>
#include <math.h>

#define NPB   120000                 // points per batch
#define NB    8                      // batches
#define NPTS  (NPB*NB)               // 960000
#define GX    704
#define GY    800
#define GZ    20
#define BIGC  (GX*GY*GZ)             // 11,264,000 cells per batch
#define MAXV  40000
#define MAXP  10
#define SENT  0x7FFFFFFF

// Hash table: per-batch open addressing, 64-bit entry = (value << 24) | lid
// value = leader point index (phase 1/2) then voxel slot (after k_assign).
#define HBITS 18
#define HSIZE (1 << HBITS)           // 262144 buckets per batch (>= 120000 pts, no overflow)
#define HMASK (HSIZE - 1)
#define EMPTY 0xFFFFFFFFFFFFFFFFull
#define LIDMASK 0xFFFFFFull          // lid < 11,264,000 < 2^24 (and != 0xFFFFFF)
#define OVERCAP 0xFFFFF              // slot marker for leaders ranked >= MAXV

#define CHUNK 1024                   // points per scan chunk
#define CPB   ((NPB + CHUNK - 1) / CHUNK)   // 118 chunks per batch

// Output layout (float32), concatenated in reference return order:
#define OFF_VOX 0                          // 8*40000*10*4 = 12,800,000
#define OFF_NP  12800000                   // 8*40000      =    320,000
#define OFF_CO  13120000                   // 8*40000*4    =  1,280,000
#define OFF_GS  14400000                   // 3

// Scratch (device globals: allocation-free per harness rules)
__device__ unsigned long long g_hash[NB * HSIZE];    // 16 MB  (L2-resident)
__device__ int           g_vox [NB * MAXV * MAXP];   // 12.8 MB (L2-resident)
__device__ int           g_key [NPTS];               // per-batch lid (or SENT)
__device__ unsigned char g_flag[NPTS];               // leader flag per point
__device__ int           g_coff[NB * CPB];           // per-chunk leader counts -> exclusive offsets

__device__ __forceinline__ unsigned hash_lid(int lid) {
    return ((unsigned)lid * 0x9E3779B1u) >> (32 - HBITS);
}

// K0: linear clear of hash table + voxel lists
__global__ void k_clear() {
    int i = blockIdx.x * blockDim.x + threadIdx.x;
    if (i < NB * HSIZE) g_hash[i] = EMPTY;                 // 2.10M entries
    if (i < NB * MAXV * MAXP) g_vox[i] = SENT;             // 3.20M entries
}

// K1: compute cell keys AND hash-insert min point index per cell (fused).
__global__ void k_prep(const float* __restrict__ pts, int n) {
    int i = blockIdx.x * blockDim.x + threadIdx.x;
    if (i >= n) return;
    float x = pts[i*5 + 1];
    float y = pts[i*5 + 2];
    float z = pts[i*5 + 3];
    // match XLA: floor((p - pc_min) / vsize), IEEE division regardless of fast-math
    int cx = (int)floorf(__fdiv_rn(__fadd_rn(x,  0.0f), 0.1f));
    int cy = (int)floorf(__fdiv_rn(__fadd_rn(y, 40.0f), 0.1f));
    int cz = (int)floorf(__fdiv_rn(__fadd_rn(z,  3.0f), 0.2f));
    int key = SENT;
    if (cx >= 0 && cx < GX && cy >= 0 && cy < GY && cz >= 0 && cz < GZ) {
        int lid = (cz * GY + cy) * GX + cx;
        key = lid;
        int b  = i / NPB;
        int li = i - b * NPB;
        unsigned long long* tab = g_hash + (size_t)b * HSIZE;
        unsigned long long  pk  = ((unsigned long long)li << 24) | (unsigned)lid;
        unsigned h = hash_lid(lid);
        while (true) {
            unsigned long long cur = tab[h];
            if (cur == EMPTY) {
                unsigned long long old = atomicCAS(&tab[h], EMPTY, pk);
                if (old == EMPTY) break;        // claimed bucket
                cur = old;
            }
            if ((unsigned)(cur & LIDMASK) == (unsigned)lid) {
                atomicMin(&tab[h], pk);         // same lid bits: min over idx
                break;
            }
            h = (h + 1) & HMASK;
        }
    }
    g_key[i] = key;
}

// K2: leader flags + per-chunk leader counts. One block per 1024-point chunk.
__global__ void k_flags() {
    int blk  = blockIdx.x;
    int b    = blk / CPB, c = blk % CPB;
    int base = b * NPB + c * CHUNK;
    int lim  = b * NPB + NPB;
    int t    = threadIdx.x;
    int p0   = base + t * 4;
    const unsigned long long* tab = g_hash + (size_t)b * HSIZE;

    int cnt = 0;
    #pragma unroll
    for (int j = 0; j < 4; j++) {
        int i = p0 + j;
        if (i >= lim) break;
        unsigned char fl = 0;
        int lid = g_key[i];
        if (lid != SENT) {
            unsigned h = hash_lid(lid);
            unsigned long long cur;
            while ((unsigned)((cur = tab[h]) & LIDMASK) != (unsigned)lid)
                h = (h + 1) & HMASK;
            fl = ((int)(cur >> 24) == (i - b * NPB));
        }
        g_flag[i] = fl;
        cnt += fl;
    }

    // block reduce (256 threads = 8 warps)
    int lane = t & 31, wid = t >> 5;
    int v = cnt;
    #pragma unroll
    for (int o = 16; o > 0; o >>= 1) v += __shfl_down_sync(0xFFFFFFFFu, v, o);
    __shared__ int ws[8];
    if (lane == 0) ws[wid] = v;
    __syncthreads();
    if (t == 0) {
        int s = 0;
        #pragma unroll
        for (int k = 0; k < 8; k++) s += ws[k];
        g_coff[blk] = s;
    }
}

// K3: per-batch exclusive scan over 118 chunk counts. grid=NB, block=128.
__global__ void k_scanc() {
    int b = blockIdx.x, t = threadIdx.x;
    __shared__ int s[128];
    int v = (t < CPB) ? g_coff[b * CPB + t] : 0;
    s[t] = v;
    __syncthreads();
    #pragma unroll
    for (int o = 1; o < 128; o <<= 1) {
        int u = (t >= o) ? s[t - o] : 0;
        __syncthreads();
        s[t] += u;
        __syncthreads();
    }
    if (t < CPB) g_coff[b * CPB + t] = s[t] - v;   // exclusive
}

// K4: assign first-come slots. Local scan of flags + chunk offset; leaders
// overwrite their hash entry value with the slot (or OVERCAP if >= MAXV).
__global__ void k_assign() {
    int blk  = blockIdx.x;
    int b    = blk / CPB, c = blk % CPB;
    int base = b * NPB + c * CHUNK;
    int lim  = b * NPB + NPB;
    int t    = threadIdx.x;
    int p0   = base + t * 4;
    unsigned long long* tab = g_hash + (size_t)b * HSIZE;

    unsigned char f[4];
    int cnt = 0;
    #pragma unroll
    for (int j = 0; j < 4; j++) {
        f[j] = (p0 + j < lim) ? g_flag[p0 + j] : (unsigned char)0;
        cnt += f[j];
    }

    // block exclusive scan of per-thread counts
    int lane = t & 31, wid = t >> 5;
    int v = cnt;
    #pragma unroll
    for (int o = 1; o < 32; o <<= 1) {
        int u = __shfl_up_sync(0xFFFFFFFFu, v, o);
        if (lane >= o) v += u;
    }
    __shared__ int ws[8], wexc[8];
    if (lane == 31) ws[wid] = v;
    __syncthreads();
    if (t == 0) {
        int s = 0;
        #pragma unroll
        for (int k = 0; k < 8; k++) { wexc[k] = s; s += ws[k]; }
    }
    __syncthreads();
    int run = g_coff[blk] + wexc[wid] + (v - cnt);

    #pragma unroll
    for (int j = 0; j < 4; j++) {
        if (f[j]) {
            int i   = p0 + j;
            int lid = g_key[i];
            int slot = (run < MAXV) ? run : OVERCAP;
            unsigned h = hash_lid(lid);
            while ((unsigned)(tab[h] & LIDMASK) != (unsigned)lid)
                h = (h + 1) & HMASK;
            // sole writer of this bucket; lid bits preserved for concurrent probes
            tab[h] = ((unsigned long long)slot << 24) | (unsigned)lid;
            run++;
        }
    }
}

// K5: lock-free sorted insertion of point index into its voxel's 10-entry list.
// Final state = 10 smallest original indices in ascending order (deterministic).
__global__ void k_insert(int n) {
    int i = blockIdx.x * blockDim.x + threadIdx.x;
    if (i >= n) return;
    int lid = g_key[i];
    if (lid == SENT) return;
    int b = i / NPB;
    const unsigned long long* tab = g_hash + (size_t)b * HSIZE;
    unsigned h = hash_lid(lid);
    unsigned long long cur;
    while ((unsigned)((cur = tab[h]) & LIDMASK) != (unsigned)lid)
        h = (h + 1) & HMASK;
    int s = (int)(cur >> 24);
    if (s >= MAXV) return;
    int* list = &g_vox[((size_t)b * MAXV + s) * MAXP];
    int carry = i - b * NPB;
    #pragma unroll
    for (int j = 0; j < MAXP; j++) {
        int old = atomicMin(&list[j], carry);
        if (old == SENT) break;              // took an empty tail slot
        carry = (old > carry) ? old : carry; // displaced value moves right
    }
}

// K6: write all outputs (covers every element; d_out is poisoned)
__global__ void k_fill(const float* __restrict__ pts, float* __restrict__ out) {
    int v = blockIdx.x * blockDim.x + threadIdx.x;
    if (v == 0) {
        out[OFF_GS + 0] = 704.0f;
        out[OFF_GS + 1] = 800.0f;
        out[OFF_GS + 2] = 20.0f;
    }
    if (v >= NB * MAXV) return;
    int b = v / MAXV;
    const int* list = &g_vox[(size_t)v * MAXP];
    float* vox = out + OFF_VOX + (size_t)v * MAXP * 4;
    int cnt = 0;
    int idx0 = list[0];
    #pragma unroll
    for (int j = 0; j < MAXP; j++) {
        int idx = list[j];
        float4 r = make_float4(0.f, 0.f, 0.f, 0.f);
        if (idx != SENT) {
            const float* p = pts + (size_t)(b * NPB + idx) * 5 + 1;
            r = make_float4(p[0], p[1], p[2], p[3]);
            cnt++;
        }
        ((float4*)vox)[j] = r;   // 160B-aligned base per voxel
    }
    out[OFF_NP + v] = (float)cnt;

    float cb = (float)b, cz = -1.f, cy = -1.f, cx = -1.f;
    if (cnt > 0) {
        int lid = g_key[b * NPB + idx0];     // per-batch lid
        int x  = lid % GX;
        int t2 = lid / GX;
        int y  = t2 % GY;
        int z  = t2 / GY;
        cz = (float)z; cy = (float)y; cx = (float)x;
    }
    float4* cr = (float4*)(out + OFF_CO + (size_t)v * 4);
    *cr = make_float4(cb, cz, cy, cx);
}

extern "C" void kernel_launch(void* const* d_in, const int* in_sizes, int n_in,
                              void* d_out, int out_size) {
    const float* pts = (const float*)d_in[0];
    int n = in_sizes[0] / 5;                 // 960000
    float* out = (float*)d_out;

    const int T = 256;
    int clear_work = NB * MAXV * MAXP;       // 3.2M (covers hash 2.1M too)

    k_clear <<<(clear_work + T - 1) / T, T>>>();
    k_prep  <<<(n + T - 1) / T, T>>>(pts, n);
    k_flags <<<NB * CPB, T>>>();
    k_scanc <<<NB, 128>>>();
    k_assign<<<NB * CPB, T>>>();
    k_insert<<<(n + T - 1) / T, T>>>(n);
    k_fill  <<<(NB * MAXV + T - 1) / T, T>>>(pts, out);
}

// round 6
// speedup vs baseline: 5.0355x; 1.2261x over previous
#include <cuda_runtime.h>
#include <math.h>

#define NPB   120000                 // points per batch
#define NB    8                      // batches
#define NPTS  (NPB*NB)               // 960000
#define GX    704
#define GY    800
#define GZ    20
#define MAXV  40000
#define MAXP  10
#define SENT  0x7FFFFFFF

// Hash table: per-batch open addressing, 64-bit entry.
//   phase 1 (prep):  (leader_idx << 24) | lid
//   phase 2 (slot):  (1<<63) | (slot << 24) | lid      (slot = OVERCAP if rank >= MAXV)
#define HBITS 18
#define HSIZE (1 << HBITS)           // 262144 buckets per batch
#define HMASK (HSIZE - 1)
#define EMPTY 0xFFFFFFFFFFFFFFFFull
#define LIDMASK 0xFFFFFFull          // lid < 11,264,000 < 2^24
#define OVERCAP 0xFFFFF

#define CHUNK 1024                   // points per scan chunk
#define CPB   ((NPB + CHUNK - 1) / CHUNK)   // 118 chunks per batch
#define NBLK  (NB * CPB)                    // 944 blocks in k_slot

// Output layout (float32), concatenated in reference return order:
#define OFF_VOX 0                          // 8*40000*10*4 = 12,800,000
#define OFF_NP  12800000                   // 8*40000      =    320,000
#define OFF_CO  13120000                   // 8*40000*4    =  1,280,000
#define OFF_GS  14400000                   // 3

// Scratch (device globals; 16B-aligned via vector element types)
__device__ ulonglong2 g_hash2[(NB * HSIZE) / 2];        // 16 MB  (L2-resident)
__device__ int4       g_vox4 [(NB * MAXV * MAXP) / 4];  // 12.8 MB (L2-resident)
__device__ int        g_bkt  [NPTS];                    // bucket index per point (-1 invalid)
__device__ unsigned   g_stat [NBLK];                    // lookback: state<<30 | sum

__device__ __forceinline__ unsigned hash_lid(int lid) {
    return ((unsigned)lid * 0x9E3779B1u) >> (32 - HBITS);
}

// K0: vectorized clear of hash + vox lists + lookback state + coors defaults + grid_size
__global__ void k_clear(float* __restrict__ out) {
    int i = blockIdx.x * blockDim.x + threadIdx.x;
    if (i < (NB * HSIZE) / 2)       g_hash2[i] = make_ulonglong2(EMPTY, EMPTY);
    if (i < (NB * MAXV * MAXP) / 4) g_vox4[i]  = make_int4(SENT, SENT, SENT, SENT);
    if (i < NB * MAXV) {
        float b = (float)(i / MAXV);
        ((float4*)(out + OFF_CO))[i] = make_float4(b, -1.f, -1.f, -1.f);
    }
    if (i < NBLK) g_stat[i] = 0u;
    if (i == 0) {
        out[OFF_GS + 0] = 704.0f;
        out[OFF_GS + 1] = 800.0f;
        out[OFF_GS + 2] = 20.0f;
    }
}

// K1: compute cell, hash-insert min point index per cell, remember bucket.
__global__ void k_prep(const float* __restrict__ pts, int n) {
    int i = blockIdx.x * blockDim.x + threadIdx.x;
    if (i >= n) return;
    float x = pts[i*5 + 1];
    float y = pts[i*5 + 2];
    float z = pts[i*5 + 3];
    // match XLA: floor((p - pc_min) / vsize), IEEE division regardless of fast-math
    int cx = (int)floorf(__fdiv_rn(__fadd_rn(x,  0.0f), 0.1f));
    int cy = (int)floorf(__fdiv_rn(__fadd_rn(y, 40.0f), 0.1f));
    int cz = (int)floorf(__fdiv_rn(__fadd_rn(z,  3.0f), 0.2f));
    int bkt = -1;
    if (cx >= 0 && cx < GX && cy >= 0 && cy < GY && cz >= 0 && cz < GZ) {
        int lid = (cz * GY + cy) * GX + cx;
        int b   = i / NPB;
        int li  = i - b * NPB;
        unsigned long long* tab = (unsigned long long*)g_hash2 + (size_t)b * HSIZE;
        unsigned long long  pk  = ((unsigned long long)li << 24) | (unsigned)lid;
        unsigned h = hash_lid(lid);
        while (true) {
            unsigned long long cur = tab[h];
            if (cur == EMPTY) {
                unsigned long long old = atomicCAS(&tab[h], EMPTY, pk);
                if (old == EMPTY) break;        // claimed bucket
                cur = old;
            }
            if ((unsigned)(cur & LIDMASK) == (unsigned)(pk & LIDMASK)) {
                atomicMin(&tab[h], pk);         // same lid: min over point index
                break;
            }
            h = (h + 1) & HMASK;
        }
        bkt = (int)h;
    }
    g_bkt[i] = bkt;
}

// K2 (fused): leader flags -> decoupled-lookback scan -> slot assign (+coors) -> insert.
// One block per 1024-point chunk; 4 points per thread.
__global__ void __launch_bounds__(256) k_slot(float* __restrict__ out) {
    const int blk  = blockIdx.x;
    const int b    = blk / CPB, c = blk - b * CPB;
    const int t    = threadIdx.x;
    const int base = b * NPB + c * CHUNK;
    const int lim  = b * NPB + NPB;
    const int p0   = base + t * 4;
    unsigned long long* tab = (unsigned long long*)g_hash2 + (size_t)b * HSIZE;
    int* vox = (int*)g_vox4;

    // ---- Phase A: leader flags (full 64-bit compare: slot-form has bit 63 set,
    //      so a concurrently rewritten bucket can never alias a point index) ----
    int  bk[4];
    unsigned long long cur[4];
    int  f[4];
    int  cnt = 0;
    #pragma unroll
    for (int j = 0; j < 4; j++) {
        int i = p0 + j;
        f[j] = 0; bk[j] = -1;
        if (i < lim) {
            bk[j] = g_bkt[i];
            if (bk[j] >= 0) {
                cur[j] = tab[bk[j]];
                f[j] = ((cur[j] >> 24) == (unsigned long long)(i - b * NPB));
            }
        }
        cnt += f[j];
    }

    // ---- block exclusive scan of per-thread leader counts (8 warps) ----
    int lane = t & 31, wid = t >> 5;
    int v = cnt;
    #pragma unroll
    for (int o = 1; o < 32; o <<= 1) {
        int u = __shfl_up_sync(0xFFFFFFFFu, v, o);
        if (lane >= o) v += u;
    }
    __shared__ int ws[8];
    __shared__ int sh_total, sh_prefix;
    if (lane == 31) ws[wid] = v;
    __syncthreads();
    if (t == 0) {
        int s = 0;
        #pragma unroll
        for (int k = 0; k < 8; k++) { int tmp = ws[k]; ws[k] = s; s += tmp; }
        sh_total = s;
        // publish aggregate (or inclusive for chunk 0) ASAP
        unsigned st = ((c == 0 ? 2u : 1u) << 30) | (unsigned)s;
        atomicExch(&g_stat[blk], st);
    }
    __syncthreads();
    int run_excl = ws[wid] + (v - cnt);
    int total    = sh_total;

    // ---- Phase B: warp-parallel decoupled lookback (warp 0) ----
    if (c == 0) {
        if (t == 0) sh_prefix = 0;
    } else if (t < 32) {
        int prefix = 0;
        int p = c;
        while (p > 0) {
            int lo = p - 32; if (lo < 0) lo = 0;
            int idx = lo + t;
            bool act = idx < p;
            unsigned st = 0;
            if (act) {
                do { st = *(volatile unsigned*)&g_stat[b * CPB + idx]; }
                while ((st >> 30) == 0u);
            }
            unsigned mask2 = __ballot_sync(0xFFFFFFFFu, act && (st >> 30) == 2u);
            if (mask2) {
                int top = 31 - __clz(mask2);     // deepest lane with inclusive prefix
                int contrib = (act && t >= top) ? (int)(st & 0x3FFFFFFFu) : 0;
                prefix += __reduce_add_sync(0xFFFFFFFFu, contrib);
                break;
            } else {
                int contrib = act ? (int)(st & 0x3FFFFFFFu) : 0;
                prefix += __reduce_add_sync(0xFFFFFFFFu, contrib);
                p = lo;
            }
        }
        if (t == 0) {
            atomicExch(&g_stat[blk], (2u << 30) | (unsigned)(prefix + total));
            sh_prefix = prefix;
        }
    }
    __syncthreads();

    // ---- Phase C: assign slots to this chunk's leaders; leaders write coors ----
    int run = sh_prefix + run_excl;
    #pragma unroll
    for (int j = 0; j < 4; j++) {
        if (f[j]) {
            int slot = (run < MAXV) ? run : OVERCAP;
            unsigned lid = (unsigned)(cur[j] & LIDMASK);
            atomicExch(&tab[bk[j]],
                       (1ull << 63) | ((unsigned long long)slot << 24) | lid);
            if (slot < MAXV) {
                int x  = lid % GX;
                int t2 = lid / GX;
                int y  = t2 % GY;
                int z  = t2 / GY;
                ((float4*)(out + OFF_CO))[b * MAXV + slot] =
                    make_float4((float)b, (float)z, (float)y, (float)x);
            }
            run++;
        }
    }
    __syncthreads();   // same-chunk leaders assigned before same-chunk inserts

    // ---- Phase D: insert points. Leader chunk <= own chunk, so spinning on
    //      bit 63 only waits on lower block IDs (always scheduled no later). ----
    #pragma unroll
    for (int j = 0; j < 4; j++) {
        int i = p0 + j;
        if (i < lim && bk[j] >= 0) {
            unsigned long long e;
            do { e = *(volatile unsigned long long*)&tab[bk[j]]; }
            while (!(e >> 63));
            int slot = (int)((e >> 24) & 0xFFFFF);
            if (slot < MAXV) {
                int* list = &vox[((size_t)b * MAXV + slot) * MAXP];
                int carry = i - b * NPB;
                #pragma unroll
                for (int q = 0; q < MAXP; q++) {
                    int old = atomicMin(&list[q], carry);
                    if (old == SENT) break;              // took empty tail slot
                    carry = (old > carry) ? old : carry; // displaced value moves right
                }
            }
        }
    }
}

// K3: write voxels + num_points (coors/grid already written)
__global__ void k_fill(const float* __restrict__ pts, float* __restrict__ out) {
    int v = blockIdx.x * blockDim.x + threadIdx.x;
    if (v >= NB * MAXV) return;
    int b = v / MAXV;
    const int* list = (const int*)g_vox4 + (size_t)v * MAXP;
    float* voxo = out + OFF_VOX + (size_t)v * MAXP * 4;
    int cnt = 0;
    #pragma unroll
    for (int j = 0; j < MAXP; j++) {
        int idx = list[j];
        float4 r = make_float4(0.f, 0.f, 0.f, 0.f);
        if (idx != SENT) {
            const float* p = pts + (size_t)(b * NPB + idx) * 5 + 1;
            r = make_float4(p[0], p[1], p[2], p[3]);
            cnt++;
        }
        ((float4*)voxo)[j] = r;   // 160B-aligned base per voxel
    }
    out[OFF_NP + v] = (float)cnt;
}

extern "C" void kernel_launch(void* const* d_in, const int* in_sizes, int n_in,
                              void* d_out, int out_size) {
    const float* pts = (const float*)d_in[0];
    int n = in_sizes[0] / 5;                 // 960000
    float* out = (float*)d_out;

    const int T = 256;
    k_clear<<<((NB * HSIZE) / 2 + T - 1) / T, T>>>(out);   // 4096 blocks covers all clears
    k_prep <<<(n + T - 1) / T, T>>>(pts, n);
    k_slot <<<NBLK, T>>>(out);
    k_fill <<<(NB * MAXV + T - 1) / T, T>>>(pts, out);
}

// round 7
// speedup vs baseline: 5.7202x; 1.1360x over previous
#include <cuda_runtime.h>
#include <math.h>

#define NPB   120000                 // points per batch
#define NB    8                      // batches
#define NPTS  (NPB*NB)               // 960000
#define GX    704
#define GY    800
#define GZ    20
#define MAXV  40000
#define MAXP  10
#define SENT  0x7FFFFFFF

// Hash table: per-batch open addressing, 64-bit entry.
//   phase 1 (prep):  (leader_idx << 24) | lid
//   phase 2 (slot):  (1<<63) | (slot << 24) | lid      (slot = OVERCAP if rank >= MAXV)
#define HBITS 18
#define HSIZE (1 << HBITS)           // 262144 buckets per batch
#define HMASK (HSIZE - 1)
#define EMPTY 0xFFFFFFFFFFFFFFFFull
#define LIDMASK 0xFFFFFFull          // lid < 11,264,000 < 2^24
#define OVERCAP 0xFFFFF

#define CHUNK 1024                   // points per scan chunk
#define CPB   ((NPB + CHUNK - 1) / CHUNK)   // 118 chunks per batch
#define NBLK  (NB * CPB)                    // 944 blocks in k_slot

// Output layout (float32), concatenated in reference return order:
#define OFF_VOX 0                          // 8*40000*10*4 = 12,800,000
#define OFF_NP  12800000                   // 8*40000      =    320,000
#define OFF_CO  13120000                   // 8*40000*4    =  1,280,000
#define OFF_GS  14400000                   // 3

// Scratch (device globals; 16B-aligned via vector element types)
__device__ ulonglong2 g_hash2[(NB * HSIZE) / 2];        // 16 MB  (L2-resident)
__device__ int4       g_vox4 [(NB * MAXV * MAXP) / 4];  // 12.8 MB (L2-resident)
__device__ int        g_bkt  [NPTS];                    // bucket index per point (-1 invalid)
__device__ int        g_cnt  [NB * MAXV];               // points per voxel (uncapped)
__device__ unsigned   g_stat [NBLK];                    // lookback: state<<30 | sum

__device__ __forceinline__ unsigned hash_lid(int lid) {
    return ((unsigned)lid * 0x9E3779B1u) >> (32 - HBITS);
}

// K0: vectorized clear of hash + vox lists + counters + lookback + coors defaults + grid_size
__global__ void k_clear(float* __restrict__ out) {
    int i = blockIdx.x * blockDim.x + threadIdx.x;
    if (i < (NB * HSIZE) / 2)       g_hash2[i] = make_ulonglong2(EMPTY, EMPTY);
    if (i < (NB * MAXV * MAXP) / 4) g_vox4[i]  = make_int4(SENT, SENT, SENT, SENT);
    if (i < NB * MAXV) {
        g_cnt[i] = 0;
        float b = (float)(i / MAXV);
        ((float4*)(out + OFF_CO))[i] = make_float4(b, -1.f, -1.f, -1.f);
    }
    if (i < NBLK) g_stat[i] = 0u;
    if (i == 0) {
        out[OFF_GS + 0] = 704.0f;
        out[OFF_GS + 1] = 800.0f;
        out[OFF_GS + 2] = 20.0f;
    }
}

// K1: compute cell, hash-insert min point index per cell, remember bucket.
// Points staged through shared memory for fully coalesced global loads.
__global__ void __launch_bounds__(256) k_prep(const float* __restrict__ pts, int n) {
    __shared__ float sp[256 * 5];
    int blk0 = blockIdx.x * 256;          // first point of this block
    int t    = threadIdx.x;

    // cooperative coalesced load: 320 float4s = 1280 floats = 256 points
    const float4* src = (const float4*)(pts + (size_t)blk0 * 5);
    int nf4 = (n - blk0 >= 256) ? 320 : ((n - blk0) * 5 + 3) / 4;
    #pragma unroll
    for (int k = 0; k < 2; k++) {
        int q = t + k * 256;
        if (q < nf4) ((float4*)sp)[q] = src[q];
    }
    __syncthreads();

    int i = blk0 + t;
    if (i >= n) return;
    float x = sp[t*5 + 1];
    float y = sp[t*5 + 2];
    float z = sp[t*5 + 3];
    // match XLA: floor((p - pc_min) / vsize), IEEE division regardless of fast-math
    int cx = (int)floorf(__fdiv_rn(__fadd_rn(x,  0.0f), 0.1f));
    int cy = (int)floorf(__fdiv_rn(__fadd_rn(y, 40.0f), 0.1f));
    int cz = (int)floorf(__fdiv_rn(__fadd_rn(z,  3.0f), 0.2f));
    int bkt = -1;
    if (cx >= 0 && cx < GX && cy >= 0 && cy < GY && cz >= 0 && cz < GZ) {
        int lid = (cz * GY + cy) * GX + cx;
        int b   = i / NPB;
        int li  = i - b * NPB;
        unsigned long long* tab = (unsigned long long*)g_hash2 + (size_t)b * HSIZE;
        unsigned long long  pk  = ((unsigned long long)li << 24) | (unsigned)lid;
        unsigned h = hash_lid(lid);
        while (true) {
            unsigned long long cur = tab[h];
            if (cur == EMPTY) {
                unsigned long long old = atomicCAS(&tab[h], EMPTY, pk);
                if (old == EMPTY) break;        // claimed bucket
                cur = old;
            }
            if ((unsigned)(cur & LIDMASK) == (unsigned)(pk & LIDMASK)) {
                atomicMin(&tab[h], pk);         // same lid: min over point index
                break;
            }
            h = (h + 1) & HMASK;
        }
        bkt = (int)h;
    }
    g_bkt[i] = bkt;
}

// K2 (fused): leader flags -> decoupled-lookback scan -> slot assign (+coors) -> insert.
// One block per 1024-point chunk; 4 points per thread.
__global__ void __launch_bounds__(256) k_slot(float* __restrict__ out) {
    const int blk  = blockIdx.x;
    const int b    = blk / CPB, c = blk - b * CPB;
    const int t    = threadIdx.x;
    const int base = b * NPB + c * CHUNK;
    const int lim  = b * NPB + NPB;
    const int p0   = base + t * 4;
    unsigned long long* tab = (unsigned long long*)g_hash2 + (size_t)b * HSIZE;
    int* vox = (int*)g_vox4;

    // ---- Phase A: leader flags (full 64-bit compare: slot-form has bit 63 set,
    //      so a concurrently rewritten bucket can never alias a point index) ----
    int  bk[4];
    unsigned long long cur[4];
    int  f[4];
    int  cnt = 0;
    #pragma unroll
    for (int j = 0; j < 4; j++) {
        int i = p0 + j;
        f[j] = 0; bk[j] = -1;
        if (i < lim) {
            bk[j] = g_bkt[i];
            if (bk[j] >= 0) {
                cur[j] = tab[bk[j]];
                f[j] = ((cur[j] >> 24) == (unsigned long long)(i - b * NPB));
            }
        }
        cnt += f[j];
    }

    // ---- block exclusive scan of per-thread leader counts (8 warps) ----
    int lane = t & 31, wid = t >> 5;
    int v = cnt;
    #pragma unroll
    for (int o = 1; o < 32; o <<= 1) {
        int u = __shfl_up_sync(0xFFFFFFFFu, v, o);
        if (lane >= o) v += u;
    }
    __shared__ int ws[8];
    __shared__ int sh_total, sh_prefix;
    if (lane == 31) ws[wid] = v;
    __syncthreads();
    if (t == 0) {
        int s = 0;
        #pragma unroll
        for (int k = 0; k < 8; k++) { int tmp = ws[k]; ws[k] = s; s += tmp; }
        sh_total = s;
        // publish aggregate (or inclusive for chunk 0) ASAP
        unsigned st = ((c == 0 ? 2u : 1u) << 30) | (unsigned)s;
        atomicExch(&g_stat[blk], st);
    }
    __syncthreads();
    int run_excl = ws[wid] + (v - cnt);
    int total    = sh_total;

    // ---- Phase B: warp-parallel decoupled lookback (warp 0) ----
    if (c == 0) {
        if (t == 0) sh_prefix = 0;
    } else if (t < 32) {
        int prefix = 0;
        int p = c;
        while (p > 0) {
            int lo = p - 32; if (lo < 0) lo = 0;
            int idx = lo + t;
            bool act = idx < p;
            unsigned st = 0;
            if (act) {
                do { st = *(volatile unsigned*)&g_stat[b * CPB + idx]; }
                while ((st >> 30) == 0u);
            }
            unsigned mask2 = __ballot_sync(0xFFFFFFFFu, act && (st >> 30) == 2u);
            if (mask2) {
                int top = 31 - __clz(mask2);     // deepest lane with inclusive prefix
                int contrib = (act && t >= top) ? (int)(st & 0x3FFFFFFFu) : 0;
                prefix += __reduce_add_sync(0xFFFFFFFFu, contrib);
                break;
            } else {
                int contrib = act ? (int)(st & 0x3FFFFFFFu) : 0;
                prefix += __reduce_add_sync(0xFFFFFFFFu, contrib);
                p = lo;
            }
        }
        if (t == 0) {
            atomicExch(&g_stat[blk], (2u << 30) | (unsigned)(prefix + total));
            sh_prefix = prefix;
        }
    }
    __syncthreads();

    // ---- Phase C: assign slots to this chunk's leaders; leaders write coors ----
    int run = sh_prefix + run_excl;
    #pragma unroll
    for (int j = 0; j < 4; j++) {
        if (f[j]) {
            int slot = (run < MAXV) ? run : OVERCAP;
            unsigned lid = (unsigned)(cur[j] & LIDMASK);
            atomicExch(&tab[bk[j]],
                       (1ull << 63) | ((unsigned long long)slot << 24) | lid);
            if (slot < MAXV) {
                int x  = lid % GX;
                int t2 = lid / GX;
                int y  = t2 % GY;
                int z  = t2 / GY;
                ((float4*)(out + OFF_CO))[b * MAXV + slot] =
                    make_float4((float)b, (float)z, (float)y, (float)x);
            }
            run++;
        }
    }
    __syncthreads();   // same-chunk leaders assigned before same-chunk inserts

    // ---- Phase D: insert points + count. Leader chunk <= own chunk, so spinning
    //      on bit 63 only waits on lower block IDs (always scheduled no later). ----
    #pragma unroll
    for (int j = 0; j < 4; j++) {
        int i = p0 + j;
        if (i < lim && bk[j] >= 0) {
            unsigned long long e;
            do { e = *(volatile unsigned long long*)&tab[bk[j]]; }
            while (!(e >> 63));
            int slot = (int)((e >> 24) & 0xFFFFF);
            if (slot < MAXV) {
                atomicAdd(&g_cnt[b * MAXV + slot], 1);
                int* list = &vox[((size_t)b * MAXV + slot) * MAXP];
                int carry = i - b * NPB;
                #pragma unroll
                for (int q = 0; q < MAXP; q++) {
                    int old = atomicMin(&list[q], carry);
                    if (old == SENT) break;              // took empty tail slot
                    carry = (old > carry) ? old : carry; // displaced value moves right
                }
            }
        }
    }
}

// K3: thread-per-row voxel fill (coalesced loads + stores) + num_points.
__global__ void __launch_bounds__(256) k_fill(const float* __restrict__ pts,
                                              float* __restrict__ out) {
    int i = blockIdx.x * blockDim.x + threadIdx.x;
    if (i < NB * MAXV) {   // num_points = min(count, MAXP)
        int c = g_cnt[i];
        out[OFF_NP + i] = (float)((c < MAXP) ? c : MAXP);
    }
    if (i >= NB * MAXV * MAXP) return;
    int idx = ((const int*)g_vox4)[i];       // coalesced 4B load
    float4 r = make_float4(0.f, 0.f, 0.f, 0.f);
    if (idx != SENT) {
        int b = i / (MAXV * MAXP);
        const float* p = pts + (size_t)(b * NPB + idx) * 5 + 1;
        r = make_float4(p[0], p[1], p[2], p[3]);
    }
    ((float4*)(out + OFF_VOX))[i] = r;       // consecutive float4 per thread
}

extern "C" void kernel_launch(void* const* d_in, const int* in_sizes, int n_in,
                              void* d_out, int out_size) {
    const float* pts = (const float*)d_in[0];
    int n = in_sizes[0] / 5;                 // 960000
    float* out = (float*)d_out;

    const int T = 256;
    k_clear<<<((NB * HSIZE) / 2 + T - 1) / T, T>>>(out);   // 4096 blocks covers all clears
    k_prep <<<(n + T - 1) / T, T>>>(pts, n);
    k_slot <<<NBLK, T>>>(out);
    k_fill <<<(NB * MAXV * MAXP + T - 1) / T, T>>>(pts, out);
}